// round 7
// baseline (speedup 1.0000x reference)
#include <cuda_runtime.h>
#include <cuda_bf16.h>
#include <math.h>
#include <stdint.h>

// ContrastiveLoss: loss = sum_i [ logsumexp_j(X_i.Y_j/T) - X_i.Y_i/T ]
// N=8192, C=512, T=0.07. tf32 mma.sync, fragment-major prepacked operands,
// persistent CTAs (grid=296, occ 2) with static fine-grained tile schedule,
// race-free 3-stage cp.async pipeline, per-(tile,warp-stripe) LSE partials.

#define NTOT 8192
#define CDIM 512
#define NCTA 296                      // 148 SMs x occ 2, exactly one wave
#define NUNITS 4096                   // 64 rowblks x 64 coltiles (128x128 tiles)
#define NCOLT 64
#define NPART (NCOLT * 4)             // 256: column tile x warpN stripe

#define XSTAGE_BYTES 16384            // 128 rows x 32 k x 4B
#define STAGE_BYTES  32768            // X + Y
#define NSTAGE 3
#define SMEM_TOTAL (NSTAGE * STAGE_BYTES)   // 98304 -> occ 2

#define PLANE_FLOATS 262144           // floats per 32-wide k-chunk plane

#define SCALE_LOG2 (14.285714285714286f * 1.4426950408889634f)
#define LN2 0.6931471805599453f

// -------- scratch (device globals; no allocation allowed) --------
__device__ __align__(16) float g_Xa[NTOT * CDIM];   // A-fragment-major, tf32-rounded
__device__ __align__(16) float g_Yb[NTOT * CDIM];   // B-fragment-major, tf32-rounded
__device__ float g_m[NPART][NTOT];    // per-stripe row max (log2 domain)
__device__ float g_l[NPART][NTOT];    // per-stripe row sum of 2^(v-max)
__device__ float g_pos[NTOT];
__device__ float g_row[NTOT];

__device__ __forceinline__ float ex2f(float x) {
    float y; asm("ex2.approx.ftz.f32 %0, %1;" : "=f"(y) : "f"(x)); return y;
}
__device__ __forceinline__ uint32_t smem_to_u32(const void* p) {
    uint32_t a;
    asm("{ .reg .u64 t; cvta.to.shared.u64 t, %1; cvt.u32.u64 %0, t; }" : "=r"(a) : "l"(p));
    return a;
}
__device__ __forceinline__ void cp_async16(uint32_t dst, const void* src) {
    asm volatile("cp.async.ca.shared.global [%0], [%1], 16;" :: "r"(dst), "l"(src) : "memory");
}
#define CP_COMMIT() asm volatile("cp.async.commit_group;" ::: "memory")
#define CP_WAIT_1() asm volatile("cp.async.wait_group 1;" ::: "memory")

__device__ __forceinline__ uint32_t tf32r(float x) {
    uint32_t r; asm("cvt.rna.tf32.f32 %0, %1;" : "=r"(r) : "f"(x)); return r;
}

__device__ __forceinline__ void mma_tf32(float* c, const uint4 a, uint32_t b0, uint32_t b1) {
    asm volatile(
        "mma.sync.aligned.m16n8k8.row.col.f32.tf32.tf32.f32 "
        "{%0,%1,%2,%3}, {%4,%5,%6,%7}, {%8,%9}, {%0,%1,%2,%3};"
        : "+f"(c[0]), "+f"(c[1]), "+f"(c[2]), "+f"(c[3])
        : "r"(a.x), "r"(a.y), "r"(a.z), "r"(a.w), "r"(b0), "r"(b1));
}

// -------- pre-kernel: tf32 round + fragment-major packing --------
__global__ void __launch_bounds__(256)
cl_pre_kernel(const float* __restrict__ X, const float* __restrict__ Y) {
    const uint32_t gid = blockIdx.x * 256u + threadIdx.x;
    const uint32_t NFRAG = (NTOT * CDIM) / 4;
    if (gid < NFRAG) {
        const uint32_t fid = gid;
        const uint32_t lane = fid & 31, s = (fid >> 5) & 3, rb = (fid >> 7) & 511, kc = fid >> 16;
        const uint32_t g = lane >> 2, q = lane & 3;
        const size_t base = (size_t)(rb * 16 + g) * CDIM + kc * 32 + s * 8 + q;
        uint4 o;
        o.x = tf32r(X[base]);
        o.y = tf32r(X[base + 8 * CDIM]);
        o.z = tf32r(X[base + 4]);
        o.w = tf32r(X[base + 8 * CDIM + 4]);
        *reinterpret_cast<uint4*>(g_Xa + (size_t)fid * 4) = o;
    } else {
        const uint32_t fid = gid - NFRAG;
        const uint32_t lane = fid & 31, kp = (fid >> 5) & 1, cb = (fid >> 6) & 1023, kc = fid >> 16;
        const uint32_t g = lane >> 2, q = lane & 3;
        const size_t base = (size_t)(cb * 8 + g) * CDIM + kc * 32 + kp * 16 + q;
        uint4 o;
        o.x = tf32r(Y[base]);
        o.y = tf32r(Y[base + 4]);
        o.z = tf32r(Y[base + 8]);
        o.w = tf32r(Y[base + 12]);
        *reinterpret_cast<uint4*>(g_Yb + (size_t)fid * 4) = o;
    }
}

// -------- main kernel: persistent, static unit schedule --------
__global__ void __launch_bounds__(256, 2)
cl_mma_kernel() {
    extern __shared__ __align__(16) char smem[];
    const uint32_t sb = smem_to_u32(smem);
    const uint4* sm4 = reinterpret_cast<const uint4*>(smem);

    const int tid = threadIdx.x;
    const int wid = tid >> 5;
    const int lane = tid & 31;
    const int g = lane >> 2;
    const int q = lane & 3;
    const int warpM = wid >> 2;       // 0..1  (64-row half)
    const int warpN = wid & 3;        // 0..3  (32-col stripe)

    const int b = blockIdx.x;
    const int njobs = (NUNITS - 1 - b) / NCTA + 1;   // 13 or 14
    const int nsteps = njobs * 16;

    // loader: flat step s -> (unit j, k-chunk kc)
    auto load_stage = [&](int s, int buf) {
        if (s < nsteps) {
            const int j = s >> 4;
            const int kc = s & 15;
            const int uid = b + NCTA * j;
            const int row0 = (uid >> 6) * 128;
            const int col0 = (uid & 63) * 128;
            const float* xsrc = g_Xa + (size_t)kc * PLANE_FLOATS + (size_t)(row0 >> 4) * 512;
            const float* ysrc = g_Yb + (size_t)kc * PLANE_FLOATS + (size_t)(col0 >> 3) * 256;
            const uint32_t xd = sb + buf * STAGE_BYTES;
            const uint32_t yd = xd + XSTAGE_BYTES;
#pragma unroll
            for (int i = 0; i < 4; i++) {
                const int c = tid + i * 256;   // 0..1023 16B-chunks
                cp_async16(xd + c * 16, xsrc + c * 4);
                cp_async16(yd + c * 16, ysrc + c * 4);
            }
        }
        CP_COMMIT();
    };

    float acc[4][4][4];

    load_stage(0, 0);
    load_stage(1, 1);

    for (int s = 0; s < nsteps; s++) {
        const int buf = s % NSTAGE;

        if ((s & 15) == 0) {
#pragma unroll
            for (int mb = 0; mb < 4; mb++)
#pragma unroll
                for (int nb = 0; nb < 4; nb++)
#pragma unroll
                    for (int c = 0; c < 4; c++) acc[mb][nb][c] = 0.0f;
        }

        // race-free: wait(stage s) -> barrier -> issue(s+2)
        CP_WAIT_1();
        __syncthreads();
        load_stage(s + 2, (s + 2) % NSTAGE);

        const uint4* Xf = sm4 + (buf * STAGE_BYTES) / 16;   // [rb(8)][sk(4)][lane]
        const uint4* Yf = Xf + XSTAGE_BYTES / 16;           // [cb(16)][kp(2)][lane]

#pragma unroll
        for (int kp = 0; kp < 2; kp++) {
            uint4 bq[4];
#pragma unroll
            for (int nb = 0; nb < 4; nb++)
                bq[nb] = Yf[((warpN * 4 + nb) * 2 + kp) * 32 + lane];
#pragma unroll
            for (int ss = 0; ss < 2; ss++) {
                const int sk = kp * 2 + ss;
#pragma unroll
                for (int mb = 0; mb < 4; mb++) {
                    const uint4 av = Xf[((warpM * 4 + mb) * 4 + sk) * 32 + lane];
#pragma unroll
                    for (int nb = 0; nb < 4; nb++) {
                        if (ss == 0) mma_tf32(acc[mb][nb], av, bq[nb].x, bq[nb].y);
                        else         mma_tf32(acc[mb][nb], av, bq[nb].z, bq[nb].w);
                    }
                }
            }
        }

        // per-unit epilogue: stripe-local (max, sum) partials, register-only
        if ((s & 15) == 15) {
            const int uid = b + NCTA * (s >> 4);
            const int row0 = (uid >> 6) * 128;
            const int ct = uid & 63;
            const int sp = ct * 4 + warpN;            // unique stripe partition
            const int col0 = ct * 128 + warpN * 32;
#pragma unroll
            for (int mb = 0; mb < 4; mb++) {
#pragma unroll
                for (int pr = 0; pr < 2; pr++) {
                    const int grow = row0 + warpM * 64 + mb * 16 + pr * 8 + g;
                    float v[8];
                    float tmax = -INFINITY;
#pragma unroll
                    for (int nb = 0; nb < 4; nb++) {
                        v[2 * nb] = acc[mb][nb][2 * pr] * SCALE_LOG2;
                        v[2 * nb + 1] = acc[mb][nb][2 * pr + 1] * SCALE_LOG2;
                        tmax = fmaxf(tmax, fmaxf(v[2 * nb], v[2 * nb + 1]));
                    }
                    tmax = fmaxf(tmax, __shfl_xor_sync(0xffffffffu, tmax, 1));
                    tmax = fmaxf(tmax, __shfl_xor_sync(0xffffffffu, tmax, 2));
                    float sum = 0.0f;
#pragma unroll
                    for (int nb = 0; nb < 4; nb++) {
                        const int gc = col0 + nb * 8 + q * 2;
                        sum += ex2f(v[2 * nb] - tmax) + ex2f(v[2 * nb + 1] - tmax);
                        if (gc == grow) g_pos[grow] = v[2 * nb];
                        if (gc + 1 == grow) g_pos[grow] = v[2 * nb + 1];
                    }
                    sum += __shfl_xor_sync(0xffffffffu, sum, 1);
                    sum += __shfl_xor_sync(0xffffffffu, sum, 2);
                    if (q == 0) {
                        g_m[sp][grow] = tmax;
                        g_l[sp][grow] = sum;
                    }
                }
            }
        }
    }
}

// -------- combine + reduce --------
__global__ void cl_combine_kernel() {
    const int i = blockIdx.x * blockDim.x + threadIdx.x;
    if (i >= NTOT) return;
    float M = -INFINITY;
#pragma unroll 8
    for (int s = 0; s < NPART; s++) M = fmaxf(M, g_m[s][i]);
    float L = 0.0f;
#pragma unroll 8
    for (int s = 0; s < NPART; s++) L += g_l[s][i] * ex2f(g_m[s][i] - M);
    g_row[i] = M + __log2f(L) - g_pos[i];
}

__global__ void cl_reduce_kernel(float* __restrict__ out) {
    __shared__ float sh[256];
    float s = 0.0f;
    for (int i = threadIdx.x; i < NTOT; i += 256) s += g_row[i];
    sh[threadIdx.x] = s;
    __syncthreads();
    for (int o = 128; o > 0; o >>= 1) {
        if (threadIdx.x < o) sh[threadIdx.x] += sh[threadIdx.x + o];
        __syncthreads();
    }
    if (threadIdx.x == 0) out[0] = sh[0] * LN2;
}

extern "C" void kernel_launch(void* const* d_in, const int* in_sizes, int n_in,
                              void* d_out, int out_size) {
    const float* X = (const float*)d_in[0];
    const float* Y = (const float*)d_in[1];
    float* out = (float*)d_out;

    cudaFuncSetAttribute(cl_mma_kernel, cudaFuncAttributeMaxDynamicSharedMemorySize, SMEM_TOTAL);

    cl_pre_kernel<<<(2 * (NTOT * CDIM) / 4) / 256, 256>>>(X, Y);
    cl_mma_kernel<<<NCTA, 256, SMEM_TOTAL>>>();
    cl_combine_kernel<<<NTOT / 256, 256>>>();
    cl_reduce_kernel<<<1, 256>>>(out);
}

// round 8
// speedup vs baseline: 1.0498x; 1.0498x over previous
#include <cuda_runtime.h>
#include <cuda_bf16.h>
#include <math.h>
#include <stdint.h>

// ContrastiveLoss: loss = sum_i [ logsumexp_j(X_i.Y_j/T) - X_i.Y_i/T ]
// N=8192, C=512, T=0.07. tf32 mma.sync, fragment-major prepacked operands,
// persistent CTAs (grid=296, occ 2), race-free deep 3-stage cp.async pipeline
// (sync -> issue -> wait2 -> compute), per-(tile,warp-stripe) LSE partials.

#define NTOT 8192
#define CDIM 512
#define NCTA 296                      // 148 SMs x occ 2, exactly one wave
#define NUNITS 4096                   // 64 rowblks x 64 coltiles (128x128 tiles)
#define NCOLT 64
#define NPART (NCOLT * 4)             // 256: column tile x warpN stripe

#define XSTAGE_BYTES 16384            // 128 rows x 32 k x 4B
#define STAGE_BYTES  32768            // X + Y
#define NSTAGE 3
#define SMEM_TOTAL (NSTAGE * STAGE_BYTES)   // 98304 -> occ 2

#define PLANE_FLOATS 262144           // floats per 32-wide k-chunk plane

#define SCALE_LOG2 (14.285714285714286f * 1.4426950408889634f)
#define LN2 0.6931471805599453f

// -------- scratch (device globals; no allocation allowed) --------
__device__ __align__(16) float g_Xa[NTOT * CDIM];   // A-fragment-major, tf32-rounded
__device__ __align__(16) float g_Yb[NTOT * CDIM];   // B-fragment-major, tf32-rounded
__device__ float g_m[NPART][NTOT];    // per-stripe row max (log2 domain)
__device__ float g_l[NPART][NTOT];    // per-stripe row sum of 2^(v-max)
__device__ float g_pos[NTOT];
__device__ float g_row[NTOT];

__device__ __forceinline__ float ex2f(float x) {
    float y; asm("ex2.approx.ftz.f32 %0, %1;" : "=f"(y) : "f"(x)); return y;
}
__device__ __forceinline__ uint32_t smem_to_u32(const void* p) {
    uint32_t a;
    asm("{ .reg .u64 t; cvta.to.shared.u64 t, %1; cvt.u32.u64 %0, t; }" : "=r"(a) : "l"(p));
    return a;
}
__device__ __forceinline__ void cp_async16(uint32_t dst, const void* src) {
    asm volatile("cp.async.ca.shared.global [%0], [%1], 16;" :: "r"(dst), "l"(src) : "memory");
}
#define CP_COMMIT() asm volatile("cp.async.commit_group;" ::: "memory")
#define CP_WAIT_2() asm volatile("cp.async.wait_group 2;" ::: "memory")

__device__ __forceinline__ uint32_t tf32r(float x) {
    uint32_t r; asm("cvt.rna.tf32.f32 %0, %1;" : "=r"(r) : "f"(x)); return r;
}

__device__ __forceinline__ void mma_tf32(float* c, const uint4 a, uint32_t b0, uint32_t b1) {
    asm volatile(
        "mma.sync.aligned.m16n8k8.row.col.f32.tf32.tf32.f32 "
        "{%0,%1,%2,%3}, {%4,%5,%6,%7}, {%8,%9}, {%0,%1,%2,%3};"
        : "+f"(c[0]), "+f"(c[1]), "+f"(c[2]), "+f"(c[3])
        : "r"(a.x), "r"(a.y), "r"(a.z), "r"(a.w), "r"(b0), "r"(b1));
}

// -------- pre-kernel: tf32 round + fragment-major packing --------
__global__ void __launch_bounds__(256)
cl_pre_kernel(const float* __restrict__ X, const float* __restrict__ Y) {
    const uint32_t gid = blockIdx.x * 256u + threadIdx.x;
    const uint32_t NFRAG = (NTOT * CDIM) / 4;
    if (gid < NFRAG) {
        const uint32_t fid = gid;
        const uint32_t lane = fid & 31, s = (fid >> 5) & 3, rb = (fid >> 7) & 511, kc = fid >> 16;
        const uint32_t g = lane >> 2, q = lane & 3;
        const size_t base = (size_t)(rb * 16 + g) * CDIM + kc * 32 + s * 8 + q;
        uint4 o;
        o.x = tf32r(X[base]);
        o.y = tf32r(X[base + 8 * CDIM]);
        o.z = tf32r(X[base + 4]);
        o.w = tf32r(X[base + 8 * CDIM + 4]);
        *reinterpret_cast<uint4*>(g_Xa + (size_t)fid * 4) = o;
    } else {
        const uint32_t fid = gid - NFRAG;
        const uint32_t lane = fid & 31, kp = (fid >> 5) & 1, cb = (fid >> 6) & 1023, kc = fid >> 16;
        const uint32_t g = lane >> 2, q = lane & 3;
        const size_t base = (size_t)(cb * 8 + g) * CDIM + kc * 32 + kp * 16 + q;
        uint4 o;
        o.x = tf32r(Y[base]);
        o.y = tf32r(Y[base + 4]);
        o.z = tf32r(Y[base + 8]);
        o.w = tf32r(Y[base + 12]);
        *reinterpret_cast<uint4*>(g_Yb + (size_t)fid * 4) = o;
    }
}

// -------- main kernel: persistent, static unit schedule --------
__global__ void __launch_bounds__(256, 2)
cl_mma_kernel() {
    extern __shared__ __align__(16) char smem[];
    const uint32_t sb = smem_to_u32(smem);
    const uint4* sm4 = reinterpret_cast<const uint4*>(smem);

    const int tid = threadIdx.x;
    const int wid = tid >> 5;
    const int lane = tid & 31;
    const int g = lane >> 2;
    const int q = lane & 3;
    const int warpM = wid >> 2;       // 0..1  (64-row half)
    const int warpN = wid & 3;        // 0..3  (32-col stripe)

    const int b = blockIdx.x;
    const int njobs = (NUNITS - 1 - b) / NCTA + 1;   // 13 or 14
    const int nsteps = njobs * 16;

    // loader: flat step s -> (unit j, k-chunk kc)
    auto load_stage = [&](int s, int buf) {
        if (s < nsteps) {
            const int j = s >> 4;
            const int kc = s & 15;
            const int uid = b + NCTA * j;
            const int row0 = (uid >> 6) * 128;
            const int col0 = (uid & 63) * 128;
            const float* xsrc = g_Xa + (size_t)kc * PLANE_FLOATS + (size_t)(row0 >> 4) * 512;
            const float* ysrc = g_Yb + (size_t)kc * PLANE_FLOATS + (size_t)(col0 >> 3) * 256;
            const uint32_t xd = sb + buf * STAGE_BYTES;
            const uint32_t yd = xd + XSTAGE_BYTES;
#pragma unroll
            for (int i = 0; i < 4; i++) {
                const int c = tid + i * 256;   // 0..1023 16B-chunks
                cp_async16(xd + c * 16, xsrc + c * 4);
                cp_async16(yd + c * 16, ysrc + c * 4);
            }
        }
        CP_COMMIT();
    };

    float acc[4][4][4];
#pragma unroll
    for (int mb = 0; mb < 4; mb++)
#pragma unroll
        for (int nb = 0; nb < 4; nb++)
#pragma unroll
            for (int c = 0; c < 4; c++) acc[mb][nb][c] = 0.0f;

    load_stage(0, 0);
    load_stage(1, 1);

    for (int s = 0; s < nsteps; s++) {
        const int buf = s % NSTAGE;

        // deep race-free pipeline: sync -> issue(s+2) -> wait(<=2 pending) -> compute(s)
        __syncthreads();
        load_stage(s + 2, (s + 2) % NSTAGE);
        CP_WAIT_2();

        const uint4* Xf = sm4 + (buf * STAGE_BYTES) / 16;   // [rb(8)][sk(4)][lane]
        const uint4* Yf = Xf + XSTAGE_BYTES / 16;           // [cb(16)][kp(2)][lane]

#pragma unroll
        for (int kp = 0; kp < 2; kp++) {
            uint4 bq[4];
#pragma unroll
            for (int nb = 0; nb < 4; nb++)
                bq[nb] = Yf[((warpN * 4 + nb) * 2 + kp) * 32 + lane];
#pragma unroll
            for (int ss = 0; ss < 2; ss++) {
                const int sk = kp * 2 + ss;
#pragma unroll
                for (int mb = 0; mb < 4; mb++) {
                    const uint4 av = Xf[((warpM * 4 + mb) * 4 + sk) * 32 + lane];
#pragma unroll
                    for (int nb = 0; nb < 4; nb++) {
                        if (ss == 0) mma_tf32(acc[mb][nb], av, bq[nb].x, bq[nb].y);
                        else         mma_tf32(acc[mb][nb], av, bq[nb].z, bq[nb].w);
                    }
                }
            }
        }

        // per-unit epilogue: stripe-local (max, sum) partials, then reset acc
        if ((s & 15) == 15) {
            const int uid = b + NCTA * (s >> 4);
            const int row0 = (uid >> 6) * 128;
            const int ct = uid & 63;
            const int sp = ct * 4 + warpN;            // unique stripe partition
            const int col0 = ct * 128 + warpN * 32;
#pragma unroll
            for (int mb = 0; mb < 4; mb++) {
#pragma unroll
                for (int pr = 0; pr < 2; pr++) {
                    const int grow = row0 + warpM * 64 + mb * 16 + pr * 8 + g;
                    float v[8];
                    float tmax = -INFINITY;
#pragma unroll
                    for (int nb = 0; nb < 4; nb++) {
                        v[2 * nb] = acc[mb][nb][2 * pr] * SCALE_LOG2;
                        v[2 * nb + 1] = acc[mb][nb][2 * pr + 1] * SCALE_LOG2;
                        tmax = fmaxf(tmax, fmaxf(v[2 * nb], v[2 * nb + 1]));
                    }
                    tmax = fmaxf(tmax, __shfl_xor_sync(0xffffffffu, tmax, 1));
                    tmax = fmaxf(tmax, __shfl_xor_sync(0xffffffffu, tmax, 2));
                    float sum = 0.0f;
#pragma unroll
                    for (int nb = 0; nb < 4; nb++) {
                        const int gc = col0 + nb * 8 + q * 2;
                        sum += ex2f(v[2 * nb] - tmax) + ex2f(v[2 * nb + 1] - tmax);
                        if (gc == grow) g_pos[grow] = v[2 * nb];
                        if (gc + 1 == grow) g_pos[grow] = v[2 * nb + 1];
                    }
                    sum += __shfl_xor_sync(0xffffffffu, sum, 1);
                    sum += __shfl_xor_sync(0xffffffffu, sum, 2);
                    if (q == 0) {
                        g_m[sp][grow] = tmax;
                        g_l[sp][grow] = sum;
                    }
                }
            }
#pragma unroll
            for (int mb = 0; mb < 4; mb++)
#pragma unroll
                for (int nb = 0; nb < 4; nb++)
#pragma unroll
                    for (int c = 0; c < 4; c++) acc[mb][nb][c] = 0.0f;
        }
    }
}

// -------- combine + reduce --------
__global__ void cl_combine_kernel() {
    const int i = blockIdx.x * blockDim.x + threadIdx.x;
    if (i >= NTOT) return;
    float M = -INFINITY;
#pragma unroll 8
    for (int s = 0; s < NPART; s++) M = fmaxf(M, g_m[s][i]);
    float L = 0.0f;
#pragma unroll 8
    for (int s = 0; s < NPART; s++) L += g_l[s][i] * ex2f(g_m[s][i] - M);
    g_row[i] = M + __log2f(L) - g_pos[i];
}

__global__ void cl_reduce_kernel(float* __restrict__ out) {
    __shared__ float sh[256];
    float s = 0.0f;
    for (int i = threadIdx.x; i < NTOT; i += 256) s += g_row[i];
    sh[threadIdx.x] = s;
    __syncthreads();
    for (int o = 128; o > 0; o >>= 1) {
        if (threadIdx.x < o) sh[threadIdx.x] += sh[threadIdx.x + o];
        __syncthreads();
    }
    if (threadIdx.x == 0) out[0] = sh[0] * LN2;
}

extern "C" void kernel_launch(void* const* d_in, const int* in_sizes, int n_in,
                              void* d_out, int out_size) {
    const float* X = (const float*)d_in[0];
    const float* Y = (const float*)d_in[1];
    float* out = (float*)d_out;

    cudaFuncSetAttribute(cl_mma_kernel, cudaFuncAttributeMaxDynamicSharedMemorySize, SMEM_TOTAL);

    cl_pre_kernel<<<(2 * (NTOT * CDIM) / 4) / 256, 256>>>(X, Y);
    cl_mma_kernel<<<NCTA, 256, SMEM_TOTAL>>>();
    cl_combine_kernel<<<NTOT / 256, 256>>>();
    cl_reduce_kernel<<<1, 256>>>(out);
}

// round 9
// speedup vs baseline: 1.1954x; 1.1387x over previous
#include <cuda_runtime.h>
#include <cuda_bf16.h>
#include <math.h>
#include <stdint.h>

// ContrastiveLoss: loss = sum_i [ logsumexp_j(X_i.Y_j/T) - X_i.Y_i/T ]
// N=8192, C=512, T=0.07. tf32 mma.sync, fragment-major prepacked operands,
// 4-warp CTAs with 64x64 warp tiles (low smem-crossbar traffic), occ 2,
// persistent CTAs (grid=296) static schedule, race-free 3-stage cp.async ring.

#define NTOT 8192
#define CDIM 512
#define NCTA 296                      // 148 SMs x occ 2, exactly one wave
#define NUNITS 4096                   // 64 rowblks x 64 coltiles (128x128 tiles)
#define NCOLT 64
#define NPART (NCOLT * 2)             // 128: column tile x warpN stripe (64 cols)

#define XSTAGE_BYTES 16384            // 128 rows x 32 k x 4B
#define STAGE_BYTES  32768            // X + Y
#define NSTAGE 3
#define SMEM_TOTAL (NSTAGE * STAGE_BYTES)   // 98304 -> occ 2 (192KB/SM)

#define PLANE_FLOATS 262144           // floats per 32-wide k-chunk plane

#define SCALE_LOG2 (14.285714285714286f * 1.4426950408889634f)
#define LN2 0.6931471805599453f

// -------- scratch (device globals; no allocation allowed) --------
__device__ __align__(16) float g_Xa[NTOT * CDIM];   // A-fragment-major, tf32-rounded
__device__ __align__(16) float g_Yb[NTOT * CDIM];   // B-fragment-major, tf32-rounded
__device__ float g_m[NPART][NTOT];    // per-stripe row max (log2 domain)
__device__ float g_l[NPART][NTOT];    // per-stripe row sum of 2^(v-max)
__device__ float g_pos[NTOT];
__device__ float g_row[NTOT];

__device__ __forceinline__ float ex2f(float x) {
    float y; asm("ex2.approx.ftz.f32 %0, %1;" : "=f"(y) : "f"(x)); return y;
}
__device__ __forceinline__ uint32_t smem_to_u32(const void* p) {
    uint32_t a;
    asm("{ .reg .u64 t; cvta.to.shared.u64 t, %1; cvt.u32.u64 %0, t; }" : "=r"(a) : "l"(p));
    return a;
}
__device__ __forceinline__ void cp_async16(uint32_t dst, const void* src) {
    asm volatile("cp.async.ca.shared.global [%0], [%1], 16;" :: "r"(dst), "l"(src) : "memory");
}
#define CP_COMMIT() asm volatile("cp.async.commit_group;" ::: "memory")
#define CP_WAIT_2() asm volatile("cp.async.wait_group 2;" ::: "memory")

__device__ __forceinline__ uint32_t tf32r(float x) {
    uint32_t r; asm("cvt.rna.tf32.f32 %0, %1;" : "=r"(r) : "f"(x)); return r;
}

__device__ __forceinline__ void mma_tf32(float* c, const uint4 a, uint32_t b0, uint32_t b1) {
    asm volatile(
        "mma.sync.aligned.m16n8k8.row.col.f32.tf32.tf32.f32 "
        "{%0,%1,%2,%3}, {%4,%5,%6,%7}, {%8,%9}, {%0,%1,%2,%3};"
        : "+f"(c[0]), "+f"(c[1]), "+f"(c[2]), "+f"(c[3])
        : "r"(a.x), "r"(a.y), "r"(a.z), "r"(a.w), "r"(b0), "r"(b1));
}

// -------- pre-kernel: tf32 round + fragment-major packing --------
__global__ void __launch_bounds__(256)
cl_pre_kernel(const float* __restrict__ X, const float* __restrict__ Y) {
    const uint32_t gid = blockIdx.x * 256u + threadIdx.x;
    const uint32_t NFRAG = (NTOT * CDIM) / 4;
    if (gid < NFRAG) {
        const uint32_t fid = gid;
        const uint32_t lane = fid & 31, s = (fid >> 5) & 3, rb = (fid >> 7) & 511, kc = fid >> 16;
        const uint32_t g = lane >> 2, q = lane & 3;
        const size_t base = (size_t)(rb * 16 + g) * CDIM + kc * 32 + s * 8 + q;
        uint4 o;
        o.x = tf32r(X[base]);
        o.y = tf32r(X[base + 8 * CDIM]);
        o.z = tf32r(X[base + 4]);
        o.w = tf32r(X[base + 8 * CDIM + 4]);
        *reinterpret_cast<uint4*>(g_Xa + (size_t)fid * 4) = o;
    } else {
        const uint32_t fid = gid - NFRAG;
        const uint32_t lane = fid & 31, kp = (fid >> 5) & 1, cb = (fid >> 6) & 1023, kc = fid >> 16;
        const uint32_t g = lane >> 2, q = lane & 3;
        const size_t base = (size_t)(cb * 8 + g) * CDIM + kc * 32 + kp * 16 + q;
        uint4 o;
        o.x = tf32r(Y[base]);
        o.y = tf32r(Y[base + 4]);
        o.z = tf32r(Y[base + 8]);
        o.w = tf32r(Y[base + 12]);
        *reinterpret_cast<uint4*>(g_Yb + (size_t)fid * 4) = o;
    }
}

// -------- main kernel: persistent, 4 warps, 64x64 warp tiles --------
__global__ void __launch_bounds__(128, 2)
cl_mma_kernel() {
    extern __shared__ __align__(16) char smem[];
    const uint32_t sb = smem_to_u32(smem);
    const uint4* sm4 = reinterpret_cast<const uint4*>(smem);

    const int tid = threadIdx.x;
    const int wid = tid >> 5;
    const int lane = tid & 31;
    const int g = lane >> 2;
    const int q = lane & 3;
    const int warpM = wid >> 1;       // 0..1  (64-row half)
    const int warpN = wid & 1;        // 0..1  (64-col stripe)

    const int b = blockIdx.x;
    const int njobs = (NUNITS - 1 - b) / NCTA + 1;   // 13 or 14
    const int nsteps = njobs * 16;

    // loader: flat step s -> (unit j, k-chunk kc); 16 cp.async16 per thread
    auto load_stage = [&](int s, int buf) {
        if (s < nsteps) {
            const int j = s >> 4;
            const int kc = s & 15;
            const int uid = b + NCTA * j;
            const int row0 = (uid >> 6) * 128;
            const int col0 = (uid & 63) * 128;
            const float* xsrc = g_Xa + (size_t)kc * PLANE_FLOATS + (size_t)(row0 >> 4) * 512;
            const float* ysrc = g_Yb + (size_t)kc * PLANE_FLOATS + (size_t)(col0 >> 3) * 256;
            const uint32_t xd = sb + buf * STAGE_BYTES;
            const uint32_t yd = xd + XSTAGE_BYTES;
#pragma unroll
            for (int i = 0; i < 8; i++) {
                const int c = tid + i * 128;   // 0..1023 16B-chunks
                cp_async16(xd + c * 16, xsrc + c * 4);
                cp_async16(yd + c * 16, ysrc + c * 4);
            }
        }
        CP_COMMIT();
    };

    float acc[4][8][4];
#pragma unroll
    for (int mb = 0; mb < 4; mb++)
#pragma unroll
        for (int nb = 0; nb < 8; nb++)
#pragma unroll
            for (int c = 0; c < 4; c++) acc[mb][nb][c] = 0.0f;

    load_stage(0, 0);
    load_stage(1, 1);

    for (int s = 0; s < nsteps; s++) {
        const int buf = s % NSTAGE;

        // race-free deep pipeline: sync -> issue(s+2) -> wait(<=2 pending) -> compute(s)
        __syncthreads();
        load_stage(s + 2, (s + 2) % NSTAGE);
        CP_WAIT_2();

        const uint4* Xf = sm4 + (buf * STAGE_BYTES) / 16;   // [rb(8)][sk(4)][lane]
        const uint4* Yf = Xf + XSTAGE_BYTES / 16;           // [cb(16)][kp(2)][lane]

#pragma unroll
        for (int kp = 0; kp < 2; kp++) {
            uint4 bq[8];
#pragma unroll
            for (int nb = 0; nb < 8; nb++)
                bq[nb] = Yf[((warpN * 8 + nb) * 2 + kp) * 32 + lane];
#pragma unroll
            for (int ss = 0; ss < 2; ss++) {
                const int sk = kp * 2 + ss;
#pragma unroll
                for (int mb = 0; mb < 4; mb++) {
                    const uint4 av = Xf[((warpM * 4 + mb) * 4 + sk) * 32 + lane];
#pragma unroll
                    for (int nb = 0; nb < 8; nb++) {
                        if (ss == 0) mma_tf32(acc[mb][nb], av, bq[nb].x, bq[nb].y);
                        else         mma_tf32(acc[mb][nb], av, bq[nb].z, bq[nb].w);
                    }
                }
            }
        }

        // per-unit epilogue: stripe-local (max, sum) partials, then reset acc
        if ((s & 15) == 15) {
            const int uid = b + NCTA * (s >> 4);
            const int row0 = (uid >> 6) * 128;
            const int ct = uid & 63;
            const int sp = ct * 2 + warpN;            // unique stripe partition
            const int col0 = ct * 128 + warpN * 64;
#pragma unroll
            for (int mb = 0; mb < 4; mb++) {
#pragma unroll
                for (int pr = 0; pr < 2; pr++) {
                    const int grow = row0 + warpM * 64 + mb * 16 + pr * 8 + g;
                    float v[16];
                    float tmax = -INFINITY;
#pragma unroll
                    for (int nb = 0; nb < 8; nb++) {
                        v[2 * nb] = acc[mb][nb][2 * pr] * SCALE_LOG2;
                        v[2 * nb + 1] = acc[mb][nb][2 * pr + 1] * SCALE_LOG2;
                        tmax = fmaxf(tmax, fmaxf(v[2 * nb], v[2 * nb + 1]));
                    }
                    tmax = fmaxf(tmax, __shfl_xor_sync(0xffffffffu, tmax, 1));
                    tmax = fmaxf(tmax, __shfl_xor_sync(0xffffffffu, tmax, 2));
                    float sum = 0.0f;
#pragma unroll
                    for (int nb = 0; nb < 8; nb++) {
                        const int gc = col0 + nb * 8 + q * 2;
                        sum += ex2f(v[2 * nb] - tmax) + ex2f(v[2 * nb + 1] - tmax);
                        if (gc == grow) g_pos[grow] = v[2 * nb];
                        if (gc + 1 == grow) g_pos[grow] = v[2 * nb + 1];
                    }
                    sum += __shfl_xor_sync(0xffffffffu, sum, 1);
                    sum += __shfl_xor_sync(0xffffffffu, sum, 2);
                    if (q == 0) {
                        g_m[sp][grow] = tmax;
                        g_l[sp][grow] = sum;
                    }
                }
            }
#pragma unroll
            for (int mb = 0; mb < 4; mb++)
#pragma unroll
                for (int nb = 0; nb < 8; nb++)
#pragma unroll
                    for (int c = 0; c < 4; c++) acc[mb][nb][c] = 0.0f;
        }
    }
}

// -------- combine + reduce --------
__global__ void cl_combine_kernel() {
    const int i = blockIdx.x * blockDim.x + threadIdx.x;
    if (i >= NTOT) return;
    float M = -INFINITY;
#pragma unroll 8
    for (int s = 0; s < NPART; s++) M = fmaxf(M, g_m[s][i]);
    float L = 0.0f;
#pragma unroll 8
    for (int s = 0; s < NPART; s++) L += g_l[s][i] * ex2f(g_m[s][i] - M);
    g_row[i] = M + __log2f(L) - g_pos[i];
}

__global__ void cl_reduce_kernel(float* __restrict__ out) {
    __shared__ float sh[256];
    float s = 0.0f;
    for (int i = threadIdx.x; i < NTOT; i += 256) s += g_row[i];
    sh[threadIdx.x] = s;
    __syncthreads();
    for (int o = 128; o > 0; o >>= 1) {
        if (threadIdx.x < o) sh[threadIdx.x] += sh[threadIdx.x + o];
        __syncthreads();
    }
    if (threadIdx.x == 0) out[0] = sh[0] * LN2;
}

extern "C" void kernel_launch(void* const* d_in, const int* in_sizes, int n_in,
                              void* d_out, int out_size) {
    const float* X = (const float*)d_in[0];
    const float* Y = (const float*)d_in[1];
    float* out = (float*)d_out;

    cudaFuncSetAttribute(cl_mma_kernel, cudaFuncAttributeMaxDynamicSharedMemorySize, SMEM_TOTAL);

    cl_pre_kernel<<<(2 * (NTOT * CDIM) / 4) / 256, 256>>>(X, Y);
    cl_mma_kernel<<<NCTA, 128, SMEM_TOTAL>>>();
    cl_combine_kernel<<<NTOT / 256, 256>>>();
    cl_reduce_kernel<<<1, 256>>>(out);
}

// round 10
// speedup vs baseline: 2.1676x; 1.8133x over previous
#include <cuda_runtime.h>
#include <cuda_fp16.h>
#include <math.h>
#include <stdint.h>

// ContrastiveLoss: loss = sum_i [ logsumexp_j(X_i.Y_j/T) - X_i.Y_i/T ]
// N=8192, C=512, T=0.07. fp16 mma.sync m16n8k16 (fp32 accum; inputs ~N(0,1) so
// fp16 is MORE precise than tf32 here), fragment-major prepacked operands,
// 4-warp CTAs / 64x64 warp tiles / occ 2, persistent grid=296 static schedule,
// race-free 3-stage cp.async ring, fused per-stripe logsumexp partials.

#define NTOT 8192
#define CDIM 512
#define NCTA 296                      // 148 SMs x occ 2, exactly one wave
#define NUNITS 4096                   // 64 rowblks x 64 coltiles (128x128 tiles)
#define NCOLT 64
#define NPART (NCOLT * 2)             // column tile x warpN stripe (64 cols)

#define STEPS_PER_UNIT 8              // step = 64-wide k chunk
#define XSTAGE_BYTES 16384            // 128 rows x 64 k x 2B
#define STAGE_BYTES  32768            // X + Y
#define NSTAGE 3
#define SMEM_TOTAL (NSTAGE * STAGE_BYTES)   // 98304 -> occ 2

#define PLANE_HALFS 524288            // halfs per 64-wide k-chunk plane (1MB)

#define SCALE_LOG2 (14.285714285714286f * 1.4426950408889634f)
#define LN2 0.6931471805599453f

// -------- scratch (device globals; no allocation allowed) --------
__device__ __align__(16) __half g_Xh[NTOT * CDIM];   // A-fragment-major fp16
__device__ __align__(16) __half g_Yh[NTOT * CDIM];   // B-fragment-major fp16
__device__ float g_m[NPART][NTOT];
__device__ float g_l[NPART][NTOT];
__device__ float g_pos[NTOT];
__device__ float g_row[NTOT];

__device__ __forceinline__ float ex2f(float x) {
    float y; asm("ex2.approx.ftz.f32 %0, %1;" : "=f"(y) : "f"(x)); return y;
}
__device__ __forceinline__ uint32_t smem_to_u32(const void* p) {
    uint32_t a;
    asm("{ .reg .u64 t; cvta.to.shared.u64 t, %1; cvt.u32.u64 %0, t; }" : "=r"(a) : "l"(p));
    return a;
}
__device__ __forceinline__ void cp_async16(uint32_t dst, const void* src) {
    asm volatile("cp.async.ca.shared.global [%0], [%1], 16;" :: "r"(dst), "l"(src) : "memory");
}
#define CP_COMMIT() asm volatile("cp.async.commit_group;" ::: "memory")
#define CP_WAIT_2() asm volatile("cp.async.wait_group 2;" ::: "memory")

__device__ __forceinline__ uint32_t pk(float a, float b) {   // low half = a (even k)
    __half2 h = __floats2half2_rn(a, b);
    return *reinterpret_cast<uint32_t*>(&h);
}

__device__ __forceinline__ void mma_f16(float* c, const uint4 a, uint32_t b0, uint32_t b1) {
    asm volatile(
        "mma.sync.aligned.m16n8k16.row.col.f32.f16.f16.f32 "
        "{%0,%1,%2,%3}, {%4,%5,%6,%7}, {%8,%9}, {%0,%1,%2,%3};"
        : "+f"(c[0]), "+f"(c[1]), "+f"(c[2]), "+f"(c[3])
        : "r"(a.x), "r"(a.y), "r"(a.z), "r"(a.w), "r"(b0), "r"(b1));
}

// -------- pre-kernel: fp16 round + fragment-major packing --------
// A fragment (kc64, rb, k16, lane(g,q)), 16B = {a0,a1,a2,a3}:
//   a0 = X[rb*16+g  ][k0+2q, +1]   a1 = X[rb*16+g+8][k0+2q, +1]
//   a2 = X[rb*16+g  ][k0+2q+8, +9] a3 = X[rb*16+g+8][k0+2q+8, +9]
// B fragment (kc64, cb, kpair, lane(g,q)), 16B = {b0,b1,b0',b1'} (two k16 halves):
//   b0 = Y[cb*8+g][k0+2q, +1]      b1 = Y[cb*8+g][k0+2q+8, +9]
//   b0'/b1' = same with k0+16
__global__ void __launch_bounds__(256)
cl_pre_kernel(const float* __restrict__ X, const float* __restrict__ Y) {
    const uint32_t gid = blockIdx.x * 256u + threadIdx.x;
    const uint32_t NFRAG = 524288;    // 16B fragments per tensor
    if (gid < NFRAG) {
        const uint32_t fid = gid;
        const uint32_t lane = fid & 31, k16 = (fid >> 5) & 3, rb = (fid >> 7) & 511, kc = fid >> 16;
        const uint32_t g = lane >> 2, q = lane & 3;
        const uint32_t k0 = kc * 64 + k16 * 16;
        const float* r0 = X + (size_t)(rb * 16 + g) * CDIM + k0;
        const float* r1 = r0 + 8 * CDIM;
        uint4 o;
        o.x = pk(r0[2 * q], r0[2 * q + 1]);
        o.y = pk(r1[2 * q], r1[2 * q + 1]);
        o.z = pk(r0[2 * q + 8], r0[2 * q + 9]);
        o.w = pk(r1[2 * q + 8], r1[2 * q + 9]);
        *reinterpret_cast<uint4*>(reinterpret_cast<char*>(g_Xh) + (size_t)fid * 16) = o;
    } else {
        const uint32_t fid = gid - NFRAG;
        const uint32_t lane = fid & 31, kp = (fid >> 5) & 1, cb = (fid >> 6) & 1023, kc = fid >> 16;
        const uint32_t g = lane >> 2, q = lane & 3;
        const uint32_t k0 = kc * 64 + kp * 32;
        const float* r = Y + (size_t)(cb * 8 + g) * CDIM + k0;
        uint4 o;
        o.x = pk(r[2 * q], r[2 * q + 1]);
        o.y = pk(r[2 * q + 8], r[2 * q + 9]);
        o.z = pk(r[16 + 2 * q], r[16 + 2 * q + 1]);
        o.w = pk(r[16 + 2 * q + 8], r[16 + 2 * q + 9]);
        *reinterpret_cast<uint4*>(reinterpret_cast<char*>(g_Yh) + (size_t)fid * 16) = o;
    }
}

// -------- main kernel: persistent, 4 warps, 64x64 warp tiles, fp16 --------
__global__ void __launch_bounds__(128, 2)
cl_mma_kernel() {
    extern __shared__ __align__(16) char smem[];
    const uint32_t sb = smem_to_u32(smem);
    const uint4* sm4 = reinterpret_cast<const uint4*>(smem);

    const int tid = threadIdx.x;
    const int wid = tid >> 5;
    const int lane = tid & 31;
    const int g = lane >> 2;
    const int q = lane & 3;
    const int warpM = wid >> 1;       // 0..1  (64-row half)
    const int warpN = wid & 1;        // 0..1  (64-col stripe)

    const int b = blockIdx.x;
    const int njobs = (NUNITS - 1 - b) / NCTA + 1;   // 13 or 14
    const int nsteps = njobs * STEPS_PER_UNIT;

    // loader: flat step s -> (unit j, 64-wide k-chunk kc)
    auto load_stage = [&](int s, int buf) {
        if (s < nsteps) {
            const int j = s >> 3;
            const int kc = s & 7;
            const int uid = b + NCTA * j;
            const int row0 = (uid >> 6) * 128;
            const int col0 = (uid & 63) * 128;
            const __half* xsrc = g_Xh + (size_t)kc * PLANE_HALFS + (size_t)(row0 >> 4) * 1024;
            const __half* ysrc = g_Yh + (size_t)kc * PLANE_HALFS + (size_t)(col0 >> 3) * 512;
            const uint32_t xd = sb + buf * STAGE_BYTES;
            const uint32_t yd = xd + XSTAGE_BYTES;
#pragma unroll
            for (int i = 0; i < 8; i++) {
                const int c = tid + i * 128;   // 0..1023 16B-chunks
                cp_async16(xd + c * 16, xsrc + c * 8);
                cp_async16(yd + c * 16, ysrc + c * 8);
            }
        }
        CP_COMMIT();
    };

    float acc[4][8][4];
#pragma unroll
    for (int mb = 0; mb < 4; mb++)
#pragma unroll
        for (int nb = 0; nb < 8; nb++)
#pragma unroll
            for (int c = 0; c < 4; c++) acc[mb][nb][c] = 0.0f;

    load_stage(0, 0);
    load_stage(1, 1);

    for (int s = 0; s < nsteps; s++) {
        const int buf = s % NSTAGE;

        // race-free deep pipeline: sync -> issue(s+2) -> wait(<=2 pending) -> compute(s)
        __syncthreads();
        load_stage(s + 2, (s + 2) % NSTAGE);
        CP_WAIT_2();

        const uint4* Xf = sm4 + (buf * STAGE_BYTES) / 16;   // [rb(8)][k16(4)][lane]
        const uint4* Yf = Xf + XSTAGE_BYTES / 16;           // [cb(16)][kpair(2)][lane]

#pragma unroll
        for (int kp = 0; kp < 2; kp++) {
            uint4 bq[8];
#pragma unroll
            for (int nb = 0; nb < 8; nb++)
                bq[nb] = Yf[((warpN * 8 + nb) * 2 + kp) * 32 + lane];
#pragma unroll
            for (int half = 0; half < 2; half++) {
                const int k16 = kp * 2 + half;
#pragma unroll
                for (int mb = 0; mb < 4; mb++) {
                    const uint4 av = Xf[((warpM * 4 + mb) * 4 + k16) * 32 + lane];
#pragma unroll
                    for (int nb = 0; nb < 8; nb++) {
                        if (half == 0) mma_f16(acc[mb][nb], av, bq[nb].x, bq[nb].y);
                        else           mma_f16(acc[mb][nb], av, bq[nb].z, bq[nb].w);
                    }
                }
            }
        }

        // per-unit epilogue: stripe-local (max, sum) partials, then reset acc
        if ((s & 7) == 7) {
            const int uid = b + NCTA * (s >> 3);
            const int row0 = (uid >> 6) * 128;
            const int ct = uid & 63;
            const int sp = ct * 2 + warpN;
            const int col0 = ct * 128 + warpN * 64;
#pragma unroll
            for (int mb = 0; mb < 4; mb++) {
#pragma unroll
                for (int pr = 0; pr < 2; pr++) {
                    const int grow = row0 + warpM * 64 + mb * 16 + pr * 8 + g;
                    float v[16];
                    float tmax = -INFINITY;
#pragma unroll
                    for (int nb = 0; nb < 8; nb++) {
                        v[2 * nb] = acc[mb][nb][2 * pr] * SCALE_LOG2;
                        v[2 * nb + 1] = acc[mb][nb][2 * pr + 1] * SCALE_LOG2;
                        tmax = fmaxf(tmax, fmaxf(v[2 * nb], v[2 * nb + 1]));
                    }
                    tmax = fmaxf(tmax, __shfl_xor_sync(0xffffffffu, tmax, 1));
                    tmax = fmaxf(tmax, __shfl_xor_sync(0xffffffffu, tmax, 2));
                    float sum = 0.0f;
#pragma unroll
                    for (int nb = 0; nb < 8; nb++) {
                        const int gc = col0 + nb * 8 + q * 2;
                        sum += ex2f(v[2 * nb] - tmax) + ex2f(v[2 * nb + 1] - tmax);
                        if (gc == grow) g_pos[grow] = v[2 * nb];
                        if (gc + 1 == grow) g_pos[grow] = v[2 * nb + 1];
                    }
                    sum += __shfl_xor_sync(0xffffffffu, sum, 1);
                    sum += __shfl_xor_sync(0xffffffffu, sum, 2);
                    if (q == 0) {
                        g_m[sp][grow] = tmax;
                        g_l[sp][grow] = sum;
                    }
                }
            }
#pragma unroll
            for (int mb = 0; mb < 4; mb++)
#pragma unroll
                for (int nb = 0; nb < 8; nb++)
#pragma unroll
                    for (int c = 0; c < 4; c++) acc[mb][nb][c] = 0.0f;
        }
    }
}

// -------- combine + reduce --------
__global__ void cl_combine_kernel() {
    const int i = blockIdx.x * blockDim.x + threadIdx.x;
    if (i >= NTOT) return;
    float M = -INFINITY;
#pragma unroll 8
    for (int s = 0; s < NPART; s++) M = fmaxf(M, g_m[s][i]);
    float L = 0.0f;
#pragma unroll 8
    for (int s = 0; s < NPART; s++) L += g_l[s][i] * ex2f(g_m[s][i] - M);
    g_row[i] = M + __log2f(L) - g_pos[i];
}

__global__ void cl_reduce_kernel(float* __restrict__ out) {
    __shared__ float sh[256];
    float s = 0.0f;
    for (int i = threadIdx.x; i < NTOT; i += 256) s += g_row[i];
    sh[threadIdx.x] = s;
    __syncthreads();
    for (int o = 128; o > 0; o >>= 1) {
        if (threadIdx.x < o) sh[threadIdx.x] += sh[threadIdx.x + o];
        __syncthreads();
    }
    if (threadIdx.x == 0) out[0] = sh[0] * LN2;
}

extern "C" void kernel_launch(void* const* d_in, const int* in_sizes, int n_in,
                              void* d_out, int out_size) {
    const float* X = (const float*)d_in[0];
    const float* Y = (const float*)d_in[1];
    float* out = (float*)d_out;

    cudaFuncSetAttribute(cl_mma_kernel, cudaFuncAttributeMaxDynamicSharedMemorySize, SMEM_TOTAL);

    cl_pre_kernel<<<4096, 256>>>(X, Y);
    cl_mma_kernel<<<NCTA, 128, SMEM_TOTAL>>>();
    cl_combine_kernel<<<NTOT / 256, 256>>>();
    cl_reduce_kernel<<<1, 256>>>(out);
}